// round 2
// baseline (speedup 1.0000x reference)
#include <cuda_runtime.h>

// Shapes fixed by the reference
#define NB   4
#define DB   8
#define CB   3
#define RB   4          // scale^2
#define KK   5
#define HH   128
#define WW   128
#define HWSZ (HH * WW)
#define PADB 2
#define TH   8                       // rows per block
#define SH_  (TH + 2 * PADB)         // 12
#define SWC  (WW + 2 * PADB)         // 132 valid halo cols
#define SSTR 136                     // smem row stride (mult of 4 -> 16B aligned float4)

__global__ __launch_bounds__(256, 2)
void adaptive_conv_ps_v2(const float* __restrict__ burst,
                         const float* __restrict__ kernels,
                         float* __restrict__ out)
{
    __shared__ float s[CB][SH_][SSTR];

    const int nd = blockIdx.z;           // 0..31
    const int h0 = blockIdx.y * TH;
    const int tx = threadIdx.x;          // 0..31 -> pixels 4tx..4tx+3
    const int ty = threadIdx.y;          // 0..7
    const int tid = ty * 32 + tx;

    // ---- stage burst tile: 3 channels, full 128-wide row span, halo 2, zero-pad ----
    const float* bptr = burst + (size_t)nd * CB * HWSZ;
    for (int idx = tid; idx < CB * SH_ * SWC; idx += 256) {
        int c   = idx / (SH_ * SWC);
        int rem = idx - c * (SH_ * SWC);
        int sh  = rem / SWC;
        int sw  = rem - sh * SWC;        // 0..131 -> global col sw-2
        int gh  = h0 + sh - PADB;
        int gw  = sw - PADB;
        float v = 0.0f;
        if (gh >= 0 && gh < HH && gw >= 0 && gw < WW)
            v = bptr[c * HWSZ + gh * WW + gw];
        s[c][sh][sw] = v;
    }
    __syncthreads();

    const int h = h0 + ty;

    float acc[CB][RB][4];
    #pragma unroll
    for (int c = 0; c < CB; c++)
        #pragma unroll
        for (int r = 0; r < RB; r++)
            #pragma unroll
            for (int p = 0; p < 4; p++)
                acc[c][r][p] = 0.0f;

    // kernels plane (nd, r*25+i*5+j) at row h; thread reads float4 at col 4tx
    const float4* kp4 = reinterpret_cast<const float4*>(
                            kernels + (size_t)nd * (RB * KK * KK) * HWSZ + (size_t)h * WW) + tx;
    const int PLANE4 = HWSZ / 4;

    #pragma unroll
    for (int i = 0; i < KK; i++) {
        // stage 8 burst floats per channel: cols 4tx .. 4tx+7 (two aligned LDS.128)
        float b[CB][8];
        #pragma unroll
        for (int c = 0; c < CB; c++) {
            float4 lo = *reinterpret_cast<const float4*>(&s[c][ty + i][4 * tx]);
            float4 hi = *reinterpret_cast<const float4*>(&s[c][ty + i][4 * tx + 4]);
            b[c][0] = lo.x; b[c][1] = lo.y; b[c][2] = lo.z; b[c][3] = lo.w;
            b[c][4] = hi.x; b[c][5] = hi.y; b[c][6] = hi.z; b[c][7] = hi.w;
        }
        #pragma unroll
        for (int j = 0; j < KK; j++) {
            #pragma unroll
            for (int r = 0; r < RB; r++) {
                const float4 kv = __ldg(kp4 + (size_t)(r * 25 + i * 5 + j) * PLANE4);
                #pragma unroll
                for (int c = 0; c < CB; c++) {
                    acc[c][r][0] = fmaf(kv.x, b[c][j + 0], acc[c][r][0]);
                    acc[c][r][1] = fmaf(kv.y, b[c][j + 1], acc[c][r][1]);
                    acc[c][r][2] = fmaf(kv.z, b[c][j + 2], acc[c][r][2]);
                    acc[c][r][3] = fmaf(kv.w, b[c][j + 3], acc[c][r][3]);
                }
            }
        }
    }

    // ---- fused pixel shuffle: out (nd, c, 2H, 2W) ----
    // pixel p at col 4tx+p maps to out cols 8tx+2p+sj; r = si*2+sj.
    // per (c,si): two STG.128 covering out cols 8tx .. 8tx+7.
    float4* o4 = reinterpret_cast<float4*>(out);
    #pragma unroll
    for (int c = 0; c < CB; c++) {
        #pragma unroll
        for (int si = 0; si < 2; si++) {
            const size_t row = ((size_t)(nd * CB + c) * (2 * HH) + (2 * h + si));
            const size_t base = row * (2 * WW / 4) + 2 * tx;
            o4[base + 0] = make_float4(acc[c][si * 2 + 0][0], acc[c][si * 2 + 1][0],
                                       acc[c][si * 2 + 0][1], acc[c][si * 2 + 1][1]);
            o4[base + 1] = make_float4(acc[c][si * 2 + 0][2], acc[c][si * 2 + 1][2],
                                       acc[c][si * 2 + 0][3], acc[c][si * 2 + 1][3]);
        }
    }
}

extern "C" void kernel_launch(void* const* d_in, const int* in_sizes, int n_in,
                              void* d_out, int out_size)
{
    const float* burst   = (const float*)d_in[0];   // (4,8,3,128,128)
    const float* kernels = (const float*)d_in[1];   // (4,8,4,5,5,128,128)
    float* out = (float*)d_out;                     // (4,8,3,256,256)

    dim3 block(32, 8, 1);
    dim3 grid(1, HH / TH, NB * DB);                 // 512 blocks, each = full-width 8-row slab
    adaptive_conv_ps_v2<<<grid, block>>>(burst, kernels, out);
}

// round 3
// speedup vs baseline: 1.3205x; 1.3205x over previous
#include <cuda_runtime.h>

// Shapes fixed by the reference
#define NB   4
#define DB   8
#define CB   3
#define RB   4          // scale^2
#define KK   5
#define HH   128
#define WW   128
#define HWSZ (HH * WW)
#define PADB 2
#define TW   32         // tile width (pixels)
#define TH   8          // tile height
#define SW_  (TW + 2 * PADB)   // 36
#define SH_  (TH + 2 * PADB)   // 12

__global__ __launch_bounds__(128, 8)
void adaptive_conv_ps_v3(const float* __restrict__ burst,
                         const float* __restrict__ kernels,
                         float* __restrict__ out)
{
    __shared__ float s[CB][SH_][SW_];

    const int nd = blockIdx.z;              // 0..31
    const int h0 = blockIdx.y * TH;
    const int w0 = blockIdx.x * TW;
    const int tx = threadIdx.x;             // 0..15 -> pixel pair (2tx, 2tx+1)
    const int ty = threadIdx.y;             // 0..7
    const int tid = ty * 16 + tx;

    // ---- stage burst tile (3 ch, halo 2, zero-pad OOB) ----
    const float* bptr = burst + (size_t)nd * CB * HWSZ;
    for (int idx = tid; idx < CB * SH_ * SW_; idx += 128) {
        int c   = idx / (SH_ * SW_);
        int rem = idx - c * (SH_ * SW_);
        int sh  = rem / SW_;
        int sw  = rem - sh * SW_;
        int gh  = h0 + sh - PADB;
        int gw  = w0 + sw - PADB;
        float v = 0.0f;
        if (gh >= 0 && gh < HH && gw >= 0 && gw < WW)
            v = bptr[c * HWSZ + gh * WW + gw];
        s[c][sh][sw] = v;
    }
    __syncthreads();

    const int h = h0 + ty;

    float acc[CB][RB][2];
    #pragma unroll
    for (int c = 0; c < CB; c++)
        #pragma unroll
        for (int r = 0; r < RB; r++) {
            acc[c][r][0] = 0.0f;
            acc[c][r][1] = 0.0f;
        }

    // kernels plane (nd, r*25+i*5+j), row h, float2 at pixel pair
    const float2* kp2 = reinterpret_cast<const float2*>(
                            kernels + (size_t)nd * (RB * KK * KK) * HWSZ + (size_t)h * WW)
                        + (w0 / 2 + tx);
    const int PLANE2 = HWSZ / 2;

    #pragma unroll
    for (int i = 0; i < KK; i++) {
        // burst window for this tap row: cols 2tx .. 2tx+5 (smem-local, halo offset included)
        float b[CB][6];
        #pragma unroll
        for (int c = 0; c < CB; c++)
            #pragma unroll
            for (int q = 0; q < 6; q++)
                b[c][q] = s[c][ty + i][2 * tx + q];

        #pragma unroll
        for (int j = 0; j < KK; j++) {
            #pragma unroll
            for (int r = 0; r < RB; r++) {
                const float2 kv = __ldcs(kp2 + (size_t)(r * 25 + i * 5 + j) * PLANE2);
                #pragma unroll
                for (int c = 0; c < CB; c++) {
                    acc[c][r][0] = fmaf(kv.x, b[c][j + 0], acc[c][r][0]);
                    acc[c][r][1] = fmaf(kv.y, b[c][j + 1], acc[c][r][1]);
                }
            }
        }
    }

    // ---- fused pixel shuffle: out (nd, c, 2H, 2W) ----
    // pixels (w0+2tx+p), r = si*2+sj -> out[2h+si][2(w0+2tx+p)+sj]
    // per (c,si): one STG.128 covering out cols 2w0+4tx .. +3
    float4* o4 = reinterpret_cast<float4*>(out);
    #pragma unroll
    for (int c = 0; c < CB; c++) {
        #pragma unroll
        for (int si = 0; si < 2; si++) {
            const size_t row = ((size_t)(nd * CB + c) * (2 * HH) + (2 * h + si));
            __stcs(&o4[row * (2 * WW / 4) + (2 * w0 + 4 * tx) / 4],
                   make_float4(acc[c][si * 2 + 0][0], acc[c][si * 2 + 1][0],
                               acc[c][si * 2 + 0][1], acc[c][si * 2 + 1][1]));
        }
    }
}

extern "C" void kernel_launch(void* const* d_in, const int* in_sizes, int n_in,
                              void* d_out, int out_size)
{
    const float* burst   = (const float*)d_in[0];   // (4,8,3,128,128)
    const float* kernels = (const float*)d_in[1];   // (4,8,4,5,5,128,128)
    float* out = (float*)d_out;                     // (4,8,3,256,256)

    dim3 block(16, 8, 1);                           // 128 threads
    dim3 grid(WW / TW, HH / TH, NB * DB);           // (4, 16, 32) = 2048 blocks
    adaptive_conv_ps_v3<<<grid, block>>>(burst, kernels, out);
}

// round 4
// speedup vs baseline: 1.4121x; 1.0694x over previous
#include <cuda_runtime.h>

// Shapes fixed by the reference
#define NB   4
#define DB   8
#define CB   3
#define RB   4
#define KK   5
#define HH   128
#define WW   128
#define HWSZ (HH * WW)
#define PADB 2
#define TW   32                     // tile width
#define TH   4                      // tile height
#define SH_  (TH + 2 * PADB)        // 8
#define SW_  (TW + 2 * PADB)        // 36

// Block: x=32 (pixel col), y=2 (si group: r = 2*si + sj), z=4 (rows). 256 threads.
__global__ __launch_bounds__(256, 8)
void adaptive_conv_ps_v4(const float* __restrict__ burst,
                         const float* __restrict__ kernels,
                         float* __restrict__ out)
{
    __shared__ float s[CB][SH_][SW_];

    const int nd = blockIdx.z;                 // 0..31
    const int h0 = blockIdx.y * TH;
    const int w0 = blockIdx.x * TW;
    const int tx = threadIdx.x;                // 0..31
    const int si = threadIdx.y;                // 0..1
    const int tz = threadIdx.z;                // 0..3
    const int tid = (tz * 2 + si) * 32 + tx;

    // ---- stage burst tile (3 ch, halo 2, zero-pad OOB): 864 elems, 256 threads ----
    const float* bptr = burst + (size_t)nd * CB * HWSZ;
    #pragma unroll
    for (int k = 0; k < 4; k++) {
        int idx = tid + k * 256;
        if (idx < CB * SH_ * SW_) {
            int c   = idx / (SH_ * SW_);
            int rem = idx - c * (SH_ * SW_);
            int sh  = rem / SW_;
            int sw  = rem - sh * SW_;
            int gh  = h0 + sh - PADB;
            int gw  = w0 + sw - PADB;
            float v = 0.0f;
            if (gh >= 0 && gh < HH && gw >= 0 && gw < WW)
                v = bptr[c * HWSZ + gh * WW + gw];
            s[c][sh][sw] = v;
        }
    }
    __syncthreads();

    const int h = h0 + tz;
    const int w = w0 + tx;

    float a00 = 0.f, a01 = 0.f;   // acc[c][sj]
    float a10 = 0.f, a11 = 0.f;
    float a20 = 0.f, a21 = 0.f;

    // kernels: (nd, r, i, j, h, w). This thread reads r = 2*si (k0) and 2*si+1 (k1).
    const float* kp = kernels + ((size_t)nd * (RB * KK * KK) + (size_t)si * (2 * KK * KK)) * HWSZ
                      + (size_t)h * WW + w;

    #pragma unroll
    for (int i = 0; i < KK; i++) {
        #pragma unroll
        for (int j = 0; j < KK; j++) {
            const int t = i * KK + j;
            const float k0 = __ldcs(kp + (size_t)t * HWSZ);
            const float k1 = __ldcs(kp + (size_t)(t + KK * KK) * HWSZ);
            const float b0 = s[0][tz + i][tx + j];
            const float b1 = s[1][tz + i][tx + j];
            const float b2 = s[2][tz + i][tx + j];
            a00 = fmaf(k0, b0, a00);  a01 = fmaf(k1, b0, a01);
            a10 = fmaf(k0, b1, a10);  a11 = fmaf(k1, b1, a11);
            a20 = fmaf(k0, b2, a20);  a21 = fmaf(k1, b2, a21);
        }
    }

    // ---- fused pixel shuffle: out (nd, c, 2H, 2W); this thread owns row 2h+si, cols 2w,2w+1 ----
    float2* o2 = reinterpret_cast<float2*>(out);
    const size_t rowbase = ((size_t)nd * CB) * (2 * HH) + (2 * h + si);
    const size_t colpair = (size_t)w;   // float2 index = (2w)/2
    __stcs(&o2[(rowbase + 0 * 2 * HH) * WW + colpair], make_float2(a00, a01));
    __stcs(&o2[(rowbase + 1 * 2 * HH) * WW + colpair], make_float2(a10, a11));
    __stcs(&o2[(rowbase + 2 * 2 * HH) * WW + colpair], make_float2(a20, a21));
}

extern "C" void kernel_launch(void* const* d_in, const int* in_sizes, int n_in,
                              void* d_out, int out_size)
{
    const float* burst   = (const float*)d_in[0];   // (4,8,3,128,128)
    const float* kernels = (const float*)d_in[1];   // (4,8,4,5,5,128,128)
    float* out = (float*)d_out;                     // (4,8,3,256,256)

    dim3 block(32, 2, 4);                           // 256 threads
    dim3 grid(WW / TW, HH / TH, NB * DB);           // (4, 32, 32) = 4096 blocks
    adaptive_conv_ps_v4<<<grid, block>>>(burst, kernels, out);
}